// round 14
// baseline (speedup 1.0000x reference)
#include <cuda_runtime.h>

// x:    [B, C, H, W] float32   flow: [B, H, W, 2] float32   out: [B, C, H, W]
// Bilinear warp, align_corners=True; identity grid folds into pixel index.
//
// Round-7 structure (2 px/thread at j-stride 32, 64x8 tile) with the row
// tap-pair (j1, j1+1) fused into one 8B LDG.64 at (o & ~1):
//   j1 even: both taps in the aligned float2 (no extra load)
//   j1 odd : hi half is q11; predicated scalar LDG fetches j1+1
// LDG.64 stays under the L1 crossbar byte floor (256B/warp << ~13 lines),
// so instruction-count halving translates directly into fewer wavefronts.

#define B_   32
#define C_   3
#define H_   512
#define W_   512
#define LOGW 9
#define HW_  (H_ * W_)
#define TILE_W 64
#define TILE_H 8

struct Px {
    unsigned a1, a2;     // 8B-aligned element offsets (rows i1, i2)
    bool parity;         // j1 & 1
    bool need_x;         // parity && j1 < W-1
    float w11, w12, w21, w22;
};

__device__ __forceinline__ Px make_px(float fi, float fj) {
    const float Hm1 = (float)(H_ - 1), Wm1 = (float)(W_ - 1);
    const float i1f = fminf(fmaxf(floorf(fi), 0.0f), Hm1);
    const float j1f = fminf(fmaxf(floorf(fj), 0.0f), Wm1);
    const float i2f = fminf(i1f + 1.0f, Hm1);
    const float di = fi - i1f;
    const float dj = fj - j1f;

    const unsigned i1 = (unsigned)i1f, i2 = (unsigned)i2f, j1 = (unsigned)j1f;

    Px p;
    p.parity = (j1 & 1u) != 0u;
    p.need_x = p.parity && (j1 < (unsigned)(W_ - 1));
    p.a1 = (i1 << LOGW) + (j1 & ~1u);
    p.a2 = (i2 << LOGW) + (j1 & ~1u);
    p.w11 = (1.0f - di) * (1.0f - dj);
    p.w21 = di * (1.0f - dj);
    p.w12 = (1.0f - di) * dj;
    p.w22 = di * dj;
    return p;
}

__device__ __forceinline__ float interp_c(const float* __restrict__ xc, const Px& p) {
    const float2 A  = __ldg(reinterpret_cast<const float2*>(xc + p.a1));
    const float2 Bv = __ldg(reinterpret_cast<const float2*>(xc + p.a2));

    float ea = 0.0f, eb = 0.0f;
    if (p.need_x) {                 // predicated straggler loads (odd j1)
        ea = __ldg(xc + p.a1 + 2);  // = x[i1][j1+1]
        eb = __ldg(xc + p.a2 + 2);  // = x[i2][j1+1]
    }

    const float q11 = p.parity ? A.y  : A.x;
    const float q21 = p.parity ? Bv.y : Bv.x;
    const float q12 = p.need_x ? ea : A.y;   // even: hi; odd edge (j1=511): hi=q11
    const float q22 = p.need_x ? eb : Bv.y;

    return q11 * p.w11 + q21 * p.w21 + q12 * p.w12 + q22 * p.w22;
}

__global__ __launch_bounds__(256)
void flow_warp_kernel(const float* __restrict__ x,
                      const float2* __restrict__ flow,
                      float* __restrict__ out)
{
    const unsigned tid  = threadIdx.x;
    const unsigned warp = tid >> 5;
    const unsigned lane = tid & 31u;

    const unsigned b  = blockIdx.z;
    const unsigned i  = blockIdx.y * TILE_H + warp;
    const unsigned j0 = blockIdx.x * TILE_W + lane;
    const unsigned j1 = j0 + 32;

    const unsigned hw0  = (i << LOGW) + j0;
    const unsigned hw1  = hw0 + 32;
    const unsigned bhw0 = (b << 18) + hw0;

    const float2 f0 = flow[bhw0];
    const float2 f1 = flow[bhw0 + 32];

    const float Hm1 = (float)(H_ - 1), Wm1 = (float)(W_ - 1);
    const float fi0 = (float)i  + Hm1 * 0.5f * f0.y;
    const float fj0 = (float)j0 + Wm1 * 0.5f * f0.x;
    const float fi1 = (float)i  + Hm1 * 0.5f * f1.y;
    const float fj1 = (float)j1 + Wm1 * 0.5f * f1.x;

    const Px p0 = make_px(fi0, fj0);
    const Px p1 = make_px(fi1, fj1);

    const unsigned base = b * (C_ * HW_);
    const float* xb = x + base;
    float* ob = out + base;

    #pragma unroll
    for (int c = 0; c < C_; ++c) {
        const float* xc = xb + c * HW_;
        ob[c * HW_ + hw0] = interp_c(xc, p0);
        ob[c * HW_ + hw1] = interp_c(xc, p1);
    }
}

extern "C" void kernel_launch(void* const* d_in, const int* in_sizes, int n_in,
                              void* d_out, int out_size)
{
    const float*  x    = (const float*)d_in[0];
    const float2* flow = (const float2*)d_in[1];
    float* out = (float*)d_out;

    dim3 grid(W_ / TILE_W, H_ / TILE_H, B_);   // (8, 64, 32)
    flow_warp_kernel<<<grid, 256>>>(x, flow, out);
}

// round 16
// speedup vs baseline: 1.1156x; 1.1156x over previous
#include <cuda_runtime.h>

// x:    [B, C, H, W] float32   flow: [B, H, W, 2] float32   out: [B, C, H, W]
// Bilinear warp, align_corners=True; identity grid folds into pixel index.
//
// Round-13 structure (scalar gathers, 2 px/thread at j-stride 32, 64x8 tile).
// Change: flow loads use __ldcs (streaming, evict-first) and output stores
// use __stcs, so the zero-reuse streams stop evicting x tap lines from L1.

#define B_   32
#define C_   3
#define H_   512
#define W_   512
#define LOGW 9
#define HW_  (H_ * W_)
#define TILE_W 64
#define TILE_H 8

__global__ __launch_bounds__(256)
void flow_warp_kernel(const float* __restrict__ x,
                      const float2* __restrict__ flow,
                      float* __restrict__ out)
{
    const unsigned tid  = threadIdx.x;
    const unsigned warp = tid >> 5;
    const unsigned lane = tid & 31u;

    const unsigned b  = blockIdx.z;
    const unsigned i  = blockIdx.y * TILE_H + warp;
    const unsigned j0 = blockIdx.x * TILE_W + lane;
    const unsigned j1 = j0 + 32;

    const unsigned hw0  = (i << LOGW) + j0;
    const unsigned hw1  = hw0 + 32;
    const unsigned bhw0 = (b << 18) + hw0;

    // streaming loads: flow has zero reuse — do not pollute L1
    const float2 f0 = __ldcs(flow + bhw0);
    const float2 f1 = __ldcs(flow + bhw0 + 32);

    const float Hm1 = (float)(H_ - 1), Wm1 = (float)(W_ - 1);
    const float fi0 = (float)i  + Hm1 * 0.5f * f0.y;
    const float fj0 = (float)j0 + Wm1 * 0.5f * f0.x;
    const float fi1 = (float)i  + Hm1 * 0.5f * f1.y;
    const float fj1 = (float)j1 + Wm1 * 0.5f * f1.x;

    // pixel 0 taps
    const float i1f0 = fminf(fmaxf(floorf(fi0), 0.0f), Hm1);
    const float j1f0 = fminf(fmaxf(floorf(fj0), 0.0f), Wm1);
    const float i2f0 = fminf(i1f0 + 1.0f, Hm1);
    const float j2f0 = fminf(j1f0 + 1.0f, Wm1);
    const float di0 = fi0 - i1f0;
    const float dj0 = fj0 - j1f0;

    // pixel 1 taps
    const float i1f1 = fminf(fmaxf(floorf(fi1), 0.0f), Hm1);
    const float j1f1 = fminf(fmaxf(floorf(fj1), 0.0f), Wm1);
    const float i2f1 = fminf(i1f1 + 1.0f, Hm1);
    const float j2f1 = fminf(j1f1 + 1.0f, Wm1);
    const float di1 = fi1 - i1f1;
    const float dj1 = fj1 - j1f1;

    const unsigned o11_0 = ((unsigned)i1f0 << LOGW) + (unsigned)j1f0;
    const unsigned o12_0 = ((unsigned)i1f0 << LOGW) + (unsigned)j2f0;
    const unsigned o21_0 = ((unsigned)i2f0 << LOGW) + (unsigned)j1f0;
    const unsigned o22_0 = ((unsigned)i2f0 << LOGW) + (unsigned)j2f0;

    const unsigned o11_1 = ((unsigned)i1f1 << LOGW) + (unsigned)j1f1;
    const unsigned o12_1 = ((unsigned)i1f1 << LOGW) + (unsigned)j2f1;
    const unsigned o21_1 = ((unsigned)i2f1 << LOGW) + (unsigned)j1f1;
    const unsigned o22_1 = ((unsigned)i2f1 << LOGW) + (unsigned)j2f1;

    const unsigned base = b * (C_ * HW_);
    const float* xb = x + base;
    float* ob = out + base;

    // batch all 24 tap loads (ptxas hoists anyway; keep explicit)
    float t[C_][8];
    #pragma unroll
    for (int c = 0; c < C_; ++c) {
        const float* xc = xb + c * HW_;
        t[c][0] = __ldg(xc + o11_0);
        t[c][1] = __ldg(xc + o21_0);
        t[c][2] = __ldg(xc + o12_0);
        t[c][3] = __ldg(xc + o22_0);
        t[c][4] = __ldg(xc + o11_1);
        t[c][5] = __ldg(xc + o21_1);
        t[c][6] = __ldg(xc + o12_1);
        t[c][7] = __ldg(xc + o22_1);
    }

    const float w11_0 = (1.0f - di0) * (1.0f - dj0);
    const float w21_0 = di0 * (1.0f - dj0);
    const float w12_0 = (1.0f - di0) * dj0;
    const float w22_0 = di0 * dj0;

    const float w11_1 = (1.0f - di1) * (1.0f - dj1);
    const float w21_1 = di1 * (1.0f - dj1);
    const float w12_1 = (1.0f - di1) * dj1;
    const float w22_1 = di1 * dj1;

    #pragma unroll
    for (int c = 0; c < C_; ++c) {
        const float q0 = t[c][0] * w11_0 + t[c][1] * w21_0
                       + t[c][2] * w12_0 + t[c][3] * w22_0;
        const float q1 = t[c][4] * w11_1 + t[c][5] * w21_1
                       + t[c][6] * w12_1 + t[c][7] * w22_1;
        __stcs(ob + c * HW_ + hw0, q0);   // streaming stores
        __stcs(ob + c * HW_ + hw1, q1);
    }
}

extern "C" void kernel_launch(void* const* d_in, const int* in_sizes, int n_in,
                              void* d_out, int out_size)
{
    const float*  x    = (const float*)d_in[0];
    const float2* flow = (const float2*)d_in[1];
    float* out = (float*)d_out;

    dim3 grid(W_ / TILE_W, H_ / TILE_H, B_);   // (8, 64, 32)
    flow_warp_kernel<<<grid, 256>>>(x, flow, out);
}